// round 7
// baseline (speedup 1.0000x reference)
#include <cuda_runtime.h>
#include <cstdint>
#include <math.h>

// Symmetric Hausdorff distance, B=4, N=M=8192, D=3, fp32.
//
// s(n,m) = cn + w - x.y  (= 0.5 d^2 >= 0), cn = 0.5|x|^2, w = 0.5|y|^2.
// hd_prep: packed arrays x4 = {x, cn}, y4 = {-y, w}; init mins to +INF bits.
// hd_main: warp owns TW=8 broadcast n-points as packed {x,x} f32x2 registers;
// lanes cover 64 consecutive m's per iteration (2 per lane, packed).
// Inner math is fma.rn.f32x2: 4 packed fma-ops + 4 FMNMX per 2 pairs.
// Col-mins: lane-exclusive shared slots -> warp-combine -> FILTERED global
// atomicMin (int bit patterns, exact for clamped nonneg floats).
// Row-mins: REDUX + filtered atomicMin once per block.
// hd_fin: out[b] = sqrt(2 * max(all mins of b)).

#define BATCH 4
#define NPTS 8192
#define MPTS 8192
#define BLOCK 128
#define NWARPS 4
#define TW 8                        // n-points per warp
#define NCHUNK (NWARPS*TW)          // 32 n per block
#define MBLK 2048                   // m-range per block
#define TILE_J 512                  // m per shared col tile
#define FINF_BITS 0x7f800000

typedef unsigned long long ull;

__device__ float4 g_x4[BATCH * NPTS];
__device__ float4 g_y4[BATCH * MPTS];
__device__ int g_rowmin[BATCH * NPTS];
__device__ int g_colmin[BATCH * MPTS];

__device__ __forceinline__ ull pack2(float a, float b) {
    ull r; asm("mov.b64 %0, {%1, %2};" : "=l"(r) : "f"(a), "f"(b)); return r;
}
__device__ __forceinline__ float2 unpack2(ull v) {
    float2 f; asm("mov.b64 {%0, %1}, %2;" : "=f"(f.x), "=f"(f.y) : "l"(v)); return f;
}
__device__ __forceinline__ ull add2(ull a, ull b) {
    ull r; asm("add.rn.f32x2 %0, %1, %2;" : "=l"(r) : "l"(a), "l"(b)); return r;
}
__device__ __forceinline__ ull fma2(ull a, ull b, ull c) {
    ull r; asm("fma.rn.f32x2 %0, %1, %2, %3;" : "=l"(r) : "l"(a), "l"(b), "l"(c)); return r;
}

__global__ void hd_prep(const float* __restrict__ pred,
                        const float* __restrict__ gt) {
    int i = blockIdx.x * blockDim.x + threadIdx.x;
    if (i >= BATCH * NPTS) return;
    float p0 = pred[3*i], p1 = pred[3*i+1], p2 = pred[3*i+2];
    g_x4[i] = make_float4(p0, p1, p2, 0.5f*(p0*p0 + p1*p1 + p2*p2));
    float q0 = gt[3*i], q1 = gt[3*i+1], q2 = gt[3*i+2];
    g_y4[i] = make_float4(-q0, -q1, -q2, 0.5f*(q0*q0 + q1*q1 + q2*q2));
    g_rowmin[i] = FINF_BITS;
    g_colmin[i] = FINF_BITS;
}

__global__ __launch_bounds__(BLOCK, 5) void hd_main() {
    __shared__ float scol[NWARPS][TILE_J];   // 8 KB; fully rewritten each tile

    const int b    = blockIdx.z;
    const int mb   = blockIdx.y;
    const int nb   = blockIdx.x;
    const int tid  = threadIdx.x;
    const int warp = tid >> 5;
    const int lane = tid & 31;
    const int nbase = b * NPTS + nb * NCHUNK + warp * TW;

    // Broadcast n-points, packed {x,x}/{cn,cn} once.
    ull X0[TW], X1[TW], X2[TW], CN[TW];
    float rmin[TW];
#pragma unroll
    for (int i = 0; i < TW; i++) {
        float4 x = g_x4[nbase + i];
        X0[i] = pack2(x.x, x.x);
        X1[i] = pack2(x.y, x.y);
        X2[i] = pack2(x.z, x.z);
        CN[i] = pack2(x.w, x.w);
        rmin[i] = __int_as_float(FINF_BITS);
    }

    const float4* __restrict__ y4 = g_y4 + b * MPTS + mb * MBLK;
    int* __restrict__ colm = g_colmin + b * MPTS + mb * MBLK;

    for (int t = 0; t < MBLK / TILE_J; t++) {
        const int jt = t * TILE_J;
#pragma unroll 1
        for (int s = 0; s < TILE_J / 64; s++) {
            const int jj = s * 64 + 2 * lane;        // tile-relative, 2 m's
            const float4 ya = y4[jt + jj];           // both LDG.128 front-batched
            const float4 yb = y4[jt + jj + 1];
            const ull Y0 = pack2(ya.x, yb.x);
            const ull Y1 = pack2(ya.y, yb.y);
            const ull Y2 = pack2(ya.z, yb.z);
            const ull W  = pack2(ya.w, yb.w);
            float ce = __int_as_float(FINF_BITS);    // col-min for even j
            float co = __int_as_float(FINF_BITS);    // col-min for odd j
#pragma unroll
            for (int i = 0; i < TW; i++) {
                ull tt = add2(CN[i], W);
                tt = fma2(X0[i], Y0, tt);
                tt = fma2(X1[i], Y1, tt);
                tt = fma2(X2[i], Y2, tt);
                float2 f = unpack2(tt);              // free: reg-pair halves
                rmin[i] = fminf(rmin[i], fminf(f.x, f.y));
                ce = fminf(ce, f.x);
                co = fminf(co, f.y);
            }
            scol[warp][jj]     = ce;                 // exclusive slots, STS.64
            scol[warp][jj + 1] = co;
        }
        __syncthreads();
        // Combine 4 warps' col partials; filtered atomic (improvers are rare).
        for (int k = tid; k < TILE_J; k += BLOCK) {
            float v = fminf(fminf(scol[0][k], scol[1][k]),
                            fminf(scol[2][k], scol[3][k]));
            int vb = __float_as_int(fmaxf(v, 0.0f));
            if (vb < colm[jt + k]) atomicMin(&colm[jt + k], vb);
        }
        __syncthreads();
    }

    // Rows: lanes covered disjoint j -> REDUX, then filtered atomic.
#pragma unroll
    for (int i = 0; i < TW; i++) {
        unsigned r = __reduce_min_sync(0xffffffffu,
                        (unsigned)__float_as_int(fmaxf(rmin[i], 0.0f)));
        if (lane == 0 && (int)r < g_rowmin[nbase + i])
            atomicMin(&g_rowmin[nbase + i], (int)r);
    }
}

__global__ void hd_fin(float* __restrict__ out) {
    __shared__ float red[256];
    const int b = blockIdx.x;
    const int tid = threadIdx.x;
    float v = 0.0f;   // all mins >= 0
    for (int i = tid; i < NPTS; i += 256)
        v = fmaxf(v, __int_as_float(g_rowmin[b * NPTS + i]));
    for (int i = tid; i < MPTS; i += 256)
        v = fmaxf(v, __int_as_float(g_colmin[b * MPTS + i]));
    red[tid] = v;
    __syncthreads();
    for (int s = 128; s > 0; s >>= 1) {
        if (tid < s) red[tid] = fmaxf(red[tid], red[tid + s]);
        __syncthreads();
    }
    if (tid == 0) out[b] = sqrtf(fmaxf(2.0f * red[0], 0.0f));
}

extern "C" void kernel_launch(void* const* d_in, const int* in_sizes, int n_in,
                              void* d_out, int out_size) {
    const float* pred = (const float*)d_in[0];
    const float* gt   = (const float*)d_in[1];
    float* out = (float*)d_out;

    hd_prep<<<(BATCH * NPTS + 255) / 256, 256>>>(pred, gt);

    dim3 grid(NPTS / NCHUNK, MPTS / MBLK, BATCH);   // (256, 4, 4) = 4096 blocks
    hd_main<<<grid, BLOCK>>>();

    hd_fin<<<BATCH, 256>>>(out);
}